// round 12
// baseline (speedup 1.0000x reference)
#include <cuda_runtime.h>
#include <cstring>

// B-spline layer via per-span cubic collapse:
//   u = 61*x, m = floor(u), t = u-m
//   out[b,f] = A0(m,f) + A1 t + A2 t^2 + A3 t^3
// A_c(m,f) = sum_r basis[m][r][c] * cp[m+r][f], bias folded into A0.
// Basis polys: host-built (double precision), passed by value (constant bank).
//
// R12 = R10 (best measured: 48 regs, shallow prefetch, FQ=32 smem quarter
// table) with RPB halved to 64 -> grid 1024 CTAs -> full 5 CTAs/SM
// residency (40 warps/SM). Occupancy was grid-capped at 3.37/SM in R10.

#define NF    128
#define FQ    32            // features per eval CTA (quarter)
#define NSPAN 61
#define TBP   256           // producer block
#define TBE   256           // eval block
#define RPB   64            // rows per eval CTA
#define UC    4             // rows per chunk
#define NCH   2             // chunks per thread (8 rows/thread)

#define TAB_ENTRIES (NSPAN * NF)            // 7808
#define QT_ENTRIES  (NSPAN * FQ)            // 1952

struct BasisTab {
    float4 b[NSPAN * 4];    // [m][r] -> (c0,c1,c2,c3) coeffs in t
};

__device__ float4 g_table[TAB_ENTRIES];     // 125 KB staging (L2-hot)

// ---- producer: fold cp + bias with basis polys -> g_table, once ----
__global__ void __launch_bounds__(TBP)
build_table_kernel(const BasisTab bt,
                   const float* __restrict__ cp,
                   const float* __restrict__ bias)
{
    const int idx = blockIdx.x * TBP + threadIdx.x;
    if (idx >= TAB_ENTRIES) return;
    const int m = idx >> 7;                 // warp-uniform -> bt reads are LDC
    const int f = idx & (NF - 1);
    const float c0 = cp[(m + 0) * NF + f];
    const float c1 = cp[(m + 1) * NF + f];
    const float c2 = cp[(m + 2) * NF + f];
    const float c3 = cp[(m + 3) * NF + f];
    const float4 b0 = bt.b[m * 4 + 0];
    const float4 b1 = bt.b[m * 4 + 1];
    const float4 b2 = bt.b[m * 4 + 2];
    const float4 b3 = bt.b[m * 4 + 3];
    float4 A;
    A.x = fmaf(c0, b0.x, fmaf(c1, b1.x, fmaf(c2, b2.x, fmaf(c3, b3.x, bias[f]))));
    A.y = fmaf(c0, b0.y, fmaf(c1, b1.y, fmaf(c2, b2.y, c3 * b3.y)));
    A.z = fmaf(c0, b0.z, fmaf(c1, b1.z, fmaf(c2, b2.z, c3 * b3.z)));
    A.w = fmaf(c0, b0.w, fmaf(c1, b1.w, fmaf(c2, b2.w, c3 * b3.w)));
    g_table[idx] = A;
}

// ---- consumer: copy quarter-table to smem, evaluate (R10 body) ----
__global__ void __launch_bounds__(TBE, 5)
bspline_eval_kernel(const float* __restrict__ x,
                    float* __restrict__ out)
{
    __shared__ float4 table[QT_ENTRIES];    // [61][32] this CTA's quarter

    const int tid  = threadIdx.x;
    const int q    = blockIdx.x & 3;        // feature quarter
    const int tile = blockIdx.x >> 2;       // row tile
    const int lane = tid & 31;              // local feature 0..31
    const int wrp  = tid >> 5;              // 0..7
    const int fg   = q * FQ + lane;         // global feature

    // ---- copy quarter of the table (coalesced LDG.128, L2-hot) ----
    {
        const float4* __restrict__ src = g_table + q * FQ;
#pragma unroll
        for (int it = 0; it < (QT_ENTRIES + TBE - 1) / TBE; it++) {
            const int idx = tid + it * TBE;
            if (idx < QT_ENTRIES) {
                const int m  = idx >> 5;
                const int ff = idx & 31;
                table[idx] = src[m * NF + ff];
            }
        }
    }
    __syncthreads();

    // ---- eval: warp owns 8 consecutive rows; 2 chunks of 4, 1-deep prefetch ----
    const int rowBase = tile * RPB + wrp * (UC * NCH);
    const float* __restrict__ xp = x + rowBase * NF + fg;
    float* __restrict__ op       = out + rowBase * NF + fg;

    float xv[UC];
#pragma unroll
    for (int j = 0; j < UC; j++)
        xv[j] = xp[j * NF];

#pragma unroll
    for (int c = 0; c < NCH; c++) {
        // prefetch next chunk's x while this chunk computes
        float xn[UC];
        if (c < NCH - 1) {
#pragma unroll
            for (int j = 0; j < UC; j++)
                xn[j] = xp[((c + 1) * UC + j) * NF];
        }

        float  t[UC];
        float4 A[UC];
#pragma unroll
        for (int j = 0; j < UC; j++) {
            const float u  = xv[j] * 61.0f;
            const float fm = floorf(u);      // x in [0,1) -> m in [0,60]
            t[j] = u - fm;
            A[j] = table[(int)fm * FQ + lane];   // conflict-free LDS.128
        }
#pragma unroll
        for (int j = 0; j < UC; j++) {
            float r = fmaf(A[j].w, t[j], A[j].z);
            r = fmaf(r, t[j], A[j].y);
            r = fmaf(r, t[j], A[j].x);
            op[(c * UC + j) * NF] = r;
        }

#pragma unroll
        for (int j = 0; j < UC; j++) xv[j] = xn[j];
    }
}

// ---- fallback for row counts not divisible by RPB ----
__global__ void __launch_bounds__(TBE)
bspline_eval_guard_kernel(const float* __restrict__ x,
                          float* __restrict__ out,
                          int B)
{
    __shared__ float4 table[QT_ENTRIES];
    const int tid  = threadIdx.x;
    const int q    = blockIdx.x & 3;
    const int tile = blockIdx.x >> 2;
    const int lane = tid & 31;
    const int wrp  = tid >> 5;
    const int fg   = q * FQ + lane;

    {
        const float4* __restrict__ src = g_table + q * FQ;
        for (int idx = tid; idx < QT_ENTRIES; idx += TBE) {
            const int m  = idx >> 5;
            const int ff = idx & 31;
            table[idx] = src[m * NF + ff];
        }
    }
    __syncthreads();

    const int rowBase = tile * RPB + wrp * (UC * NCH);
    for (int j = 0; j < UC * NCH; j++) {
        const int row = rowBase + j;
        if (row < B) {
            const float u  = x[row * NF + fg] * 61.0f;
            const float fm = floorf(u);
            const float t  = u - fm;
            const float4 A = table[(int)fm * FQ + lane];
            float r = fmaf(A.w, t, A.z);
            r = fmaf(r, t, A.y);
            r = fmaf(r, t, A.x);
            out[row * NF + fg] = r;
        }
    }
}

// ---- host-side basis polynomial construction (input-independent) ----
static inline double knotd(int im3) {
    double v = (double)im3;
    if (v < 0.0) v = 0.0;
    if (v > 61.0) v = 61.0;
    return v;
}

static void build_basis(BasisTab* bt)
{
    for (int m = 0; m < NSPAN; m++) {
        double P[4][4];
        memset(P, 0, sizeof(P));
        P[0][0] = 1.0;   // k=0: N_{m+3}^0 = 1 on the span

        for (int k = 1; k <= 3; k++) {
            double Q[4][4];
            memset(Q, 0, sizeof(Q));
            for (int j = 0; j <= k; j++) {
                const int i = m + 3 - k + j;
                const double ti   = knotd(i - 3);
                const double ti1  = knotd(i - 2);
                const double tik  = knotd(i - 3 + k);
                const double tik1 = knotd(i - 2 + k);
                if (j >= 1 && tik != ti) {
                    const double inv = 1.0 / (tik - ti);
                    const double a0  = ((double)m - ti) * inv;
                    for (int c = 0; c < 4; c++) Q[j][c]     += a0  * P[j - 1][c];
                    for (int c = 0; c < 3; c++) Q[j][c + 1] += inv * P[j - 1][c];
                }
                if (j <= k - 1 && tik1 != ti1) {
                    const double inv = 1.0 / (tik1 - ti1);
                    const double b0  = (tik1 - (double)m) * inv;
                    for (int c = 0; c < 4; c++) Q[j][c]     += b0  * P[j][c];
                    for (int c = 0; c < 3; c++) Q[j][c + 1] -= inv * P[j][c];
                }
            }
            memcpy(P, Q, sizeof(P));
        }
        for (int r = 0; r < 4; r++) {
            bt->b[m * 4 + r].x = (float)P[r][0];
            bt->b[m * 4 + r].y = (float)P[r][1];
            bt->b[m * 4 + r].z = (float)P[r][2];
            bt->b[m * 4 + r].w = (float)P[r][3];
        }
    }
}

extern "C" void kernel_launch(void* const* d_in, const int* in_sizes, int n_in,
                              void* d_out, int out_size)
{
    const float* x    = (const float*)d_in[0];
    const float* cp   = (const float*)d_in[1];
    const float* bias = (const float*)d_in[2];
    float* out = (float*)d_out;

    const int B = in_sizes[0] / NF;   // 16384 rows

    static BasisTab bt;
    build_basis(&bt);                 // deterministic per call

    // producer: build the 61x128 coefficient table once
    build_table_kernel<<<(TAB_ENTRIES + TBP - 1) / TBP, TBP>>>(bt, cp, bias);

    // consumer: evaluate (4 feature-quarters x row tiles)
    if ((B % RPB) == 0) {
        const int grid = (B / RPB) * 4;                 // 1024 CTAs
        bspline_eval_kernel<<<grid, TBE>>>(x, out);
    } else {
        const int grid = ((B + RPB - 1) / RPB) * 4;
        bspline_eval_guard_kernel<<<grid, TBE>>>(x, out, B);
    }
}

// round 13
// speedup vs baseline: 1.0060x; 1.0060x over previous
#include <cuda_runtime.h>
#include <cstring>

// B-spline layer via per-span cubic collapse:
//   u = 61*x, m = floor(u), t = u-m
//   out[b,f] = A0(m,f) + A1 t + A2 t^2 + A3 t^3
// A_c(m,f) = sum_r basis[m][r][c] * cp[m+r][f], bias folded into A0.
// Basis polys: host-built (double precision), passed by value (constant bank).
//
// R13: PERSISTENT eval CTAs. Grid 760 = 5 CTAs/SM exactly; each CTA cp.async's
// its 31.25 KB feature-quarter table into smem ONCE, then grid-strides over
// 32-row tiles (2-3 per CTA). Kills R12's per-tile copy redundancy while
// keeping full residency. x loads 1-deep pipelined across tiles.

#define NF     128
#define FQ     32            // features per eval CTA (quarter)
#define NSPAN  61
#define TBP    256           // producer block
#define TBE    256           // eval block
#define TROWS  32            // rows per tile
#define UC     4             // rows per warp per tile (8 warps * 4 = 32)
#define GRID_E 760           // 5 CTAs/SM * 152 SMs
#define QSTRIDE (GRID_E / 4) // 190 CTAs per feature quarter

#define TAB_ENTRIES (NSPAN * NF)            // 7808
#define QT_ENTRIES  (NSPAN * FQ)            // 1952

struct BasisTab {
    float4 b[NSPAN * 4];    // [m][r] -> (c0,c1,c2,c3) coeffs in t
};

__device__ float4 g_table[TAB_ENTRIES];     // 125 KB staging (L2-hot)

// ---- producer: fold cp + bias with basis polys -> g_table, once ----
__global__ void __launch_bounds__(TBP)
build_table_kernel(const BasisTab bt,
                   const float* __restrict__ cp,
                   const float* __restrict__ bias)
{
    const int idx = blockIdx.x * TBP + threadIdx.x;
    if (idx >= TAB_ENTRIES) return;
    const int m = idx >> 7;                 // warp-uniform -> bt reads are LDC
    const int f = idx & (NF - 1);
    const float c0 = cp[(m + 0) * NF + f];
    const float c1 = cp[(m + 1) * NF + f];
    const float c2 = cp[(m + 2) * NF + f];
    const float c3 = cp[(m + 3) * NF + f];
    const float4 b0 = bt.b[m * 4 + 0];
    const float4 b1 = bt.b[m * 4 + 1];
    const float4 b2 = bt.b[m * 4 + 2];
    const float4 b3 = bt.b[m * 4 + 3];
    float4 A;
    A.x = fmaf(c0, b0.x, fmaf(c1, b1.x, fmaf(c2, b2.x, fmaf(c3, b3.x, bias[f]))));
    A.y = fmaf(c0, b0.y, fmaf(c1, b1.y, fmaf(c2, b2.y, c3 * b3.y)));
    A.z = fmaf(c0, b0.z, fmaf(c1, b1.z, fmaf(c2, b2.z, c3 * b3.z)));
    A.w = fmaf(c0, b0.w, fmaf(c1, b1.w, fmaf(c2, b2.w, c3 * b3.w)));
    g_table[idx] = A;
}

__device__ __forceinline__ unsigned smem_u32(const void* p) {
    return (unsigned)__cvta_generic_to_shared(p);
}

// ---- consumer: persistent; cp.async quarter table once, then tile loop ----
__global__ void __launch_bounds__(TBE, 5)
bspline_eval_kernel(const float* __restrict__ x,
                    float* __restrict__ out,
                    int NT)                       // number of 32-row tiles
{
    __shared__ float4 table[QT_ENTRIES];    // [61][32] this CTA's quarter

    const int tid  = threadIdx.x;
    const int q    = blockIdx.x & 3;        // feature quarter
    const int t0   = blockIdx.x >> 2;       // first tile for this CTA
    const int lane = tid & 31;              // local feature 0..31
    const int wrp  = tid >> 5;              // 0..7
    const int fg   = q * FQ + lane;         // global feature

    // ---- async copy of this quarter of the table (no reg round-trip) ----
    {
        const float4* __restrict__ src = g_table + q * FQ;
#pragma unroll
        for (int it = 0; it < (QT_ENTRIES + TBE - 1) / TBE; it++) {
            const int idx = tid + it * TBE;
            if (idx < QT_ENTRIES) {
                const float4* gp = src + (idx >> 5) * NF + (idx & 31);
                asm volatile("cp.async.cg.shared.global [%0], [%1], 16;"
                             :: "r"(smem_u32(&table[idx])), "l"(gp) : "memory");
            }
        }
        asm volatile("cp.async.commit_group;" ::: "memory");
    }

    // ---- prefetch first tile's x while the table copy is in flight ----
    int t = t0;
    float xv[UC];
    if (t < NT) {
        const int rowBase = t * TROWS + wrp * UC;
#pragma unroll
        for (int j = 0; j < UC; j++)
            xv[j] = x[(rowBase + j) * NF + fg];
    }

    asm volatile("cp.async.wait_group 0;" ::: "memory");
    __syncthreads();

    // ---- persistent tile loop, 1-deep cross-tile x prefetch ----
    while (t < NT) {
        const int tn = t + QSTRIDE;
        float xn[UC];
        if (tn < NT) {
            const int rb = tn * TROWS + wrp * UC;
#pragma unroll
            for (int j = 0; j < UC; j++)
                xn[j] = x[(rb + j) * NF + fg];
        }

        const int rowBase = t * TROWS + wrp * UC;
        float  tt[UC];
        float4 A[UC];
#pragma unroll
        for (int j = 0; j < UC; j++) {
            const float u  = xv[j] * 61.0f;
            const float fm = floorf(u);          // x in [0,1) -> m in [0,60]
            tt[j] = u - fm;
            A[j]  = table[(int)fm * FQ + lane];  // conflict-free LDS.128
        }
#pragma unroll
        for (int j = 0; j < UC; j++) {
            float r = fmaf(A[j].w, tt[j], A[j].z);
            r = fmaf(r, tt[j], A[j].y);
            r = fmaf(r, tt[j], A[j].x);
            out[(rowBase + j) * NF + fg] = r;
        }

#pragma unroll
        for (int j = 0; j < UC; j++) xv[j] = xn[j];
        t = tn;
    }
}

// ---- fallback for row counts not divisible by TROWS ----
__global__ void __launch_bounds__(TBE)
bspline_eval_guard_kernel(const float* __restrict__ x,
                          float* __restrict__ out,
                          int B)
{
    __shared__ float4 table[QT_ENTRIES];
    const int tid  = threadIdx.x;
    const int q    = blockIdx.x & 3;
    const int tile = blockIdx.x >> 2;
    const int lane = tid & 31;
    const int wrp  = tid >> 5;
    const int fg   = q * FQ + lane;

    {
        const float4* __restrict__ src = g_table + q * FQ;
        for (int idx = tid; idx < QT_ENTRIES; idx += TBE) {
            table[idx] = src[(idx >> 5) * NF + (idx & 31)];
        }
    }
    __syncthreads();

    const int rowBase = tile * TROWS + wrp * UC;
    for (int j = 0; j < UC; j++) {
        const int row = rowBase + j;
        if (row < B) {
            const float u  = x[row * NF + fg] * 61.0f;
            const float fm = floorf(u);
            const float t  = u - fm;
            const float4 A = table[(int)fm * FQ + lane];
            float r = fmaf(A.w, t, A.z);
            r = fmaf(r, t, A.y);
            r = fmaf(r, t, A.x);
            out[row * NF + fg] = r;
        }
    }
}

// ---- host-side basis polynomial construction (input-independent) ----
static inline double knotd(int im3) {
    double v = (double)im3;
    if (v < 0.0) v = 0.0;
    if (v > 61.0) v = 61.0;
    return v;
}

static void build_basis(BasisTab* bt)
{
    for (int m = 0; m < NSPAN; m++) {
        double P[4][4];
        memset(P, 0, sizeof(P));
        P[0][0] = 1.0;   // k=0: N_{m+3}^0 = 1 on the span

        for (int k = 1; k <= 3; k++) {
            double Q[4][4];
            memset(Q, 0, sizeof(Q));
            for (int j = 0; j <= k; j++) {
                const int i = m + 3 - k + j;
                const double ti   = knotd(i - 3);
                const double ti1  = knotd(i - 2);
                const double tik  = knotd(i - 3 + k);
                const double tik1 = knotd(i - 2 + k);
                if (j >= 1 && tik != ti) {
                    const double inv = 1.0 / (tik - ti);
                    const double a0  = ((double)m - ti) * inv;
                    for (int c = 0; c < 4; c++) Q[j][c]     += a0  * P[j - 1][c];
                    for (int c = 0; c < 3; c++) Q[j][c + 1] += inv * P[j - 1][c];
                }
                if (j <= k - 1 && tik1 != ti1) {
                    const double inv = 1.0 / (tik1 - ti1);
                    const double b0  = (tik1 - (double)m) * inv;
                    for (int c = 0; c < 4; c++) Q[j][c]     += b0  * P[j][c];
                    for (int c = 0; c < 3; c++) Q[j][c + 1] -= inv * P[j][c];
                }
            }
            memcpy(P, Q, sizeof(P));
        }
        for (int r = 0; r < 4; r++) {
            bt->b[m * 4 + r].x = (float)P[r][0];
            bt->b[m * 4 + r].y = (float)P[r][1];
            bt->b[m * 4 + r].z = (float)P[r][2];
            bt->b[m * 4 + r].w = (float)P[r][3];
        }
    }
}

extern "C" void kernel_launch(void* const* d_in, const int* in_sizes, int n_in,
                              void* d_out, int out_size)
{
    const float* x    = (const float*)d_in[0];
    const float* cp   = (const float*)d_in[1];
    const float* bias = (const float*)d_in[2];
    float* out = (float*)d_out;

    const int B = in_sizes[0] / NF;   // 16384 rows

    static BasisTab bt;
    build_basis(&bt);                 // deterministic per call

    // producer: build the 61x128 coefficient table once
    build_table_kernel<<<(TAB_ENTRIES + TBP - 1) / TBP, TBP>>>(bt, cp, bias);

    if ((B % TROWS) == 0) {
        const int NT = B / TROWS;                       // 512 tiles
        bspline_eval_kernel<<<GRID_E, TBE>>>(x, out, NT);
    } else {
        const int grid = ((B + TROWS - 1) / TROWS) * 4;
        bspline_eval_guard_kernel<<<grid, TBE>>>(x, out, B);
    }
}